// round 5
// baseline (speedup 1.0000x reference)
#include <cuda_runtime.h>
#include <cuda_fp16.h>
#include <cstdint>

// Problem constants
#define ODIM 4096
#define IDIM 4096
#define MTOT 8192   // B*S = 4*2048
#define SEQ  2048

#define KC 64                  // K elems per chunk (64 fp16 = 128B row = SW128 atom)
#define NCHUNK (IDIM / KC)     // 64

// Arch-feature dispatch: tcgen05/cta_group only exist on sm_10xa targets.
#if defined(__CUDA_ARCH_FEAT_SM103_ALL) || defined(__CUDA_ARCH_FEAT_SM100_ALL) || defined(__CUDA_ARCH_FEAT_SM101_ALL)
#define HAS_TCGEN05 1
#else
#define HAS_TCGEN05 0
#endif

// ---- tcgen05 path layout (6 stages x (16KB A + 16KB B)) ----
#define T_STAGES 6
#define SMEM_TMEM   0
#define SMEM_FULL   8          // barriers: full (complete_tx)
#define SMEM_READY2 64         // leader-side both-ready (count=2)
#define SMEM_DONE   128        // MMA done (commit multicast)
#define SMEM_DATA   1024
#define OP_BYTES    16384      // 128 rows * 128B
#define T_SMEM_B    (SMEM_DATA + T_STAGES * OP_BYTES)
// ---- fallback path layout (4 stages x (16KB A + 32KB B)) ----
#define F_STAGES 4
#define F_STAGE_BYTES 49152
#define SMEM_EMPTY  64         // fallback empty barriers (count=256)

#define SMEM_TOTAL 197632      // both paths: 1024 + 192KB

// idesc kind::f16 cg2: dtype=F32(1<<4), atype=btype=F16(0), (N/8)<<17, (M/16)<<24
#define IDESC 0x10400010u
#define TMEM_NCOLS 256u

// Tiled, pre-swizzled operand storage (16KB per (row-tile, k-chunk), contiguous).
__device__ uint4 g_Xt[(size_t)MTOT * IDIM / 8];   // 64 MB
__device__ uint4 g_Wt[(size_t)ODIM * IDIM / 8];   // 32 MB

// ---------------------------------------------------------------------------
// helpers (all legal on plain sm_103)
// ---------------------------------------------------------------------------
__device__ __forceinline__ uint32_t smem_u32(const void* p) {
    uint32_t a;
    asm("{ .reg .u64 t; cvta.to.shared.u64 t, %1; cvt.u32.u64 %0, t; }" : "=r"(a) : "l"(p));
    return a;
}

#define SWZ(x) ((x) ^ (((x) >> 3) & 0x70))

__device__ __forceinline__ void bulk_ld(uint32_t dst, const void* src,
                                        uint32_t bytes, uint32_t mbar) {
    asm volatile(
        "cp.async.bulk.shared::cluster.global.mbarrier::complete_tx::bytes "
        "[%0], [%1], %2, [%3];"
        :: "r"(dst), "l"(src), "r"(bytes), "r"(mbar) : "memory");
}

__device__ __forceinline__ void expect_tx(uint32_t mbar, uint32_t bytes) {
    asm volatile("mbarrier.arrive.expect_tx.shared.b64 _, [%0], %1;"
                 :: "r"(mbar), "r"(bytes) : "memory");
}

__device__ __forceinline__ void mbar_init(uint32_t addr, uint32_t cnt) {
    asm volatile("mbarrier.init.shared.b64 [%0], %1;" :: "r"(addr), "r"(cnt) : "memory");
}

__device__ __forceinline__ void mbar_arrive(uint32_t addr) {
    asm volatile("mbarrier.arrive.shared.b64 _, [%0];" :: "r"(addr) : "memory");
}

__device__ __forceinline__ void mbar_wait_cta(uint32_t addr, uint32_t parity) {
    asm volatile(
        "{\n\t.reg .pred P1;\n\t"
        "WAIT_%=:\n\t"
        "mbarrier.try_wait.parity.acquire.cta.shared::cta.b64 P1, [%0], %1, 0x989680;\n\t"
        "@P1 bra.uni DONE_%=;\n\t"
        "bra.uni WAIT_%=;\n\t"
        "DONE_%=:\n\t}"
        :: "r"(addr), "r"(parity) : "memory");
}

// ---------------------------------------------------------------------------
// Prep 1: fake-quantize x -> integer-valued fp16, tiled+swizzled layout.
// ---------------------------------------------------------------------------
__global__ void quant_x_kernel(const float* __restrict__ x,
                               const float* __restrict__ act_scale) {
    int idx = blockIdx.x * blockDim.x + threadIdx.x;
    int m = idx >> 9;            // 512 chunks of 8 elems per row
    int c = idx & 511;
    const float4* xp = reinterpret_cast<const float4*>(x + (size_t)m * IDIM + c * 8);
    float4 v0 = xp[0];
    float4 v1 = xp[1];
    float s = act_scale[m & (SEQ - 1)];
    float inv = __fdiv_rn(1.0f, s);
    float q0 = fminf(fmaxf(rintf(v0.x * inv), -127.f), 127.f);
    float q1 = fminf(fmaxf(rintf(v0.y * inv), -127.f), 127.f);
    float q2 = fminf(fmaxf(rintf(v0.z * inv), -127.f), 127.f);
    float q3 = fminf(fmaxf(rintf(v0.w * inv), -127.f), 127.f);
    float q4 = fminf(fmaxf(rintf(v1.x * inv), -127.f), 127.f);
    float q5 = fminf(fmaxf(rintf(v1.y * inv), -127.f), 127.f);
    float q6 = fminf(fmaxf(rintf(v1.z * inv), -127.f), 127.f);
    float q7 = fminf(fmaxf(rintf(v1.w * inv), -127.f), 127.f);
    __half2 h0 = __floats2half2_rn(q0, q1);
    __half2 h1 = __floats2half2_rn(q2, q3);
    __half2 h2 = __floats2half2_rn(q4, q5);
    __half2 h3 = __floats2half2_rn(q6, q7);
    uint4 pk;
    pk.x = *reinterpret_cast<uint32_t*>(&h0);
    pk.y = *reinterpret_cast<uint32_t*>(&h1);
    pk.z = *reinterpret_cast<uint32_t*>(&h2);
    pk.w = *reinterpret_cast<uint32_t*>(&h3);
    int mt = m >> 7, row = m & 127, kc = c >> 3, cc = c & 7;
    g_Xt[(size_t)(mt * 64 + kc) * 1024 + (SWZ((uint32_t)(row * 128 + cc * 16)) >> 4)] = pk;
}

// ---------------------------------------------------------------------------
// Prep 2: dequantize 4-bit weights -> fp16, tiled+swizzled layout.
// ---------------------------------------------------------------------------
__global__ void dequant_w_kernel(const int* __restrict__ qw,
                                 const float* __restrict__ wscale,
                                 const int* __restrict__ wzero) {
    int idx = blockIdx.x * blockDim.x + threadIdx.x;
    int o = idx >> 9;
    int c = idx & 511;
    int4 q = reinterpret_cast<const int4*>(qw + (size_t)o * (IDIM / 2) + c * 4)[0];
    int g = c >> 4;
    float z  = (float)wzero[o * 32 + g];
    float ws = wscale[o * 32 + g];
    __half2 h0 = __floats2half2_rn(((float)(q.x & 15) - z) * ws,
                                   ((float)((q.x >> 4) & 15) - z) * ws);
    __half2 h1 = __floats2half2_rn(((float)(q.y & 15) - z) * ws,
                                   ((float)((q.y >> 4) & 15) - z) * ws);
    __half2 h2 = __floats2half2_rn(((float)(q.z & 15) - z) * ws,
                                   ((float)((q.z >> 4) & 15) - z) * ws);
    __half2 h3 = __floats2half2_rn(((float)(q.w & 15) - z) * ws,
                                   ((float)((q.w >> 4) & 15) - z) * ws);
    uint4 pk;
    pk.x = *reinterpret_cast<uint32_t*>(&h0);
    pk.y = *reinterpret_cast<uint32_t*>(&h1);
    pk.z = *reinterpret_cast<uint32_t*>(&h2);
    pk.w = *reinterpret_cast<uint32_t*>(&h3);
    int nt = o >> 7, row = o & 127, kc = c >> 3, cc = c & 7;
    g_Wt[(size_t)(nt * 64 + kc) * 1024 + (SWZ((uint32_t)(row * 128 + cc * 16)) >> 4)] = pk;
}

// ---------------------------------------------------------------------------
// GEMM: out[m,n] = s[m] * sum_k X[m,k]*W[n,k] + bias[n]
// Two device paths selected at compile time per target.
// ---------------------------------------------------------------------------
__global__ void __launch_bounds__(256, 1) __cluster_dims__(2, 1, 1)
gemm_kernel(const float* __restrict__ act_scale,
            const float* __restrict__ bias,
            float* __restrict__ out) {
    extern __shared__ char smem[];
    uint32_t sbase = smem_u32(smem);
    int tid = threadIdx.x;
    int wid = tid >> 5;
    int lid = tid & 31;

#if HAS_TCGEN05
    // =======================================================================
    // tcgen05 cg2 path: 256x256 pair tile, 6-stage bulk-DMA pipeline
    // =======================================================================
    uint32_t rank;
    asm("mov.u32 %0, %%cluster_ctarank;" : "=r"(rank));

    int pid = blockIdx.x >> 1;
    int n0 = (pid & 15) * 256;
    int m0 = (pid >> 4) * 256;
    int mtile = (m0 >> 7) + (int)rank;
    int ntile = (n0 >> 7) + (int)rank;

    if (wid == 0) {
        asm volatile("tcgen05.alloc.cta_group::2.sync.aligned.shared::cta.b32 [%0], %1;"
                     :: "r"(sbase + SMEM_TMEM), "r"(TMEM_NCOLS) : "memory");
    }
    if (tid == 0) {
#pragma unroll
        for (int s = 0; s < T_STAGES; ++s) {
            mbar_init(sbase + SMEM_FULL + 8 * s, 1u);
            mbar_init(sbase + SMEM_READY2 + 8 * s, 2u);
            mbar_init(sbase + SMEM_DONE + 8 * s, 1u);
        }
    }
    __syncthreads();
    uint32_t tmem;
    asm volatile("ld.shared.b32 %0, [%1];" : "=r"(tmem) : "r"(sbase + SMEM_TMEM));

    asm volatile("barrier.cluster.arrive.aligned;" ::: "memory");
    asm volatile("barrier.cluster.wait.aligned;" ::: "memory");

    if (tid == 0) {
        const char* Asrc = reinterpret_cast<const char*>(g_Xt + (size_t)mtile * 64 * 1024);
        const char* Bsrc = reinterpret_cast<const char*>(g_Wt + (size_t)ntile * 64 * 1024);

#pragma unroll
        for (int k = 0; k < T_STAGES; ++k) {
            uint32_t fb = sbase + SMEM_FULL + 8 * k;
            expect_tx(fb, 2 * OP_BYTES);
            bulk_ld(sbase + SMEM_DATA + k * OP_BYTES, Asrc + (size_t)k * OP_BYTES,
                    OP_BYTES, fb);
            bulk_ld(sbase + T_SMEM_B + k * OP_BYTES, Bsrc + (size_t)k * OP_BYTES,
                    OP_BYTES, fb);
        }
        asm volatile("tcgen05.fence::after_thread_sync;" ::: "memory");

        for (int k = 0; k < NCHUNK; ++k) {
            int st = k % T_STAGES;
            uint32_t par = (uint32_t)((k / T_STAGES) & 1);

            mbar_wait_cta(sbase + SMEM_FULL + 8 * st, par);
            // signal leader's ready2 (mapa to rank 0)
            asm volatile(
                "{\n\t.reg .b32 r;\n\t"
                "mapa.shared::cluster.u32 r, %0, %1;\n\t"
                "mbarrier.arrive.shared::cluster.b64 _, [r];\n\t}"
                :: "r"(sbase + SMEM_READY2 + 8 * st), "r"(0u) : "memory");

            if (rank == 0) {
                asm volatile(
                    "{\n\t.reg .pred P1;\n\t"
                    "WAIT_%=:\n\t"
                    "mbarrier.try_wait.parity.acquire.cluster.shared::cta.b64 P1, [%0], %1, 0x989680;\n\t"
                    "@P1 bra.uni DONE_%=;\n\t"
                    "bra.uni WAIT_%=;\n\t"
                    "DONE_%=:\n\t}"
                    :: "r"(sbase + SMEM_READY2 + 8 * st), "r"(par) : "memory");

                // SW128 descriptor: version=1, SBO=64, LBO=1
                const uint64_t dbase = (uint64_t(2) << 61) | (uint64_t(1) << 46) |
                                       (uint64_t(64) << 32) | (uint64_t(1) << 16);
                uint64_t ad = dbase | (((sbase + SMEM_DATA + st * OP_BYTES) >> 4) & 0x3FFF);
                uint64_t bd = dbase | (((sbase + T_SMEM_B + st * OP_BYTES) >> 4) & 0x3FFF);
#pragma unroll
                for (int kk = 0; kk < 4; ++kk) {
                    uint32_t en = (k | kk) != 0;
                    asm volatile(
                        "{\n\t.reg .pred p;\n\t"
                        "setp.ne.u32 p, %5, 0;\n\t"
                        "tcgen05.mma.cta_group::2.kind::f16 [%0], %1, %2, %3, "
                        "{%4, %4, %4, %4, %4, %4, %4, %4}, p;\n\t"
                        "}"
                        :: "r"(tmem), "l"(ad + 2 * kk), "l"(bd + 2 * kk),
                           "r"(IDESC), "r"(0u), "r"(en)
                        : "memory");
                }
                asm volatile(
                    "tcgen05.commit.cta_group::2.mbarrier::arrive::one.shared::cluster"
                    ".multicast::cluster.b64 [%0], %1;"
                    :: "r"(sbase + SMEM_DONE + 8 * st), "h"((uint16_t)3) : "memory");
            }

            if (k + T_STAGES < NCHUNK) {
                mbar_wait_cta(sbase + SMEM_DONE + 8 * st, par);
                uint32_t fb = sbase + SMEM_FULL + 8 * st;
                expect_tx(fb, 2 * OP_BYTES);
                bulk_ld(sbase + SMEM_DATA + st * OP_BYTES,
                        Asrc + (size_t)(k + T_STAGES) * OP_BYTES, OP_BYTES, fb);
                bulk_ld(sbase + T_SMEM_B + st * OP_BYTES,
                        Bsrc + (size_t)(k + T_STAGES) * OP_BYTES, OP_BYTES, fb);
            }
        }
        mbar_wait_cta(sbase + SMEM_DONE + 8 * ((NCHUNK - 1) % T_STAGES),
                      (uint32_t)(((NCHUNK - 1) / T_STAGES) & 1));
    }

    __syncthreads();
    asm volatile("tcgen05.fence::after_thread_sync;" ::: "memory");

    if (wid < 4) {
        int m = m0 + (int)rank * 128 + wid * 32 + lid;
        float s = act_scale[m & (SEQ - 1)];
#pragma unroll
        for (int h = 0; h < 4; ++h) {
            uint32_t r[64];
            asm volatile(
                "tcgen05.ld.sync.aligned.32x32b.x32.b32 "
                "{%0, %1, %2, %3, %4, %5, %6, %7, "
                " %8, %9, %10, %11, %12, %13, %14, %15, "
                " %16, %17, %18, %19, %20, %21, %22, %23, "
                " %24, %25, %26, %27, %28, %29, %30, %31}, [%32];"
                : "=r"(r[0]), "=r"(r[1]), "=r"(r[2]), "=r"(r[3]),
                  "=r"(r[4]), "=r"(r[5]), "=r"(r[6]), "=r"(r[7]),
                  "=r"(r[8]), "=r"(r[9]), "=r"(r[10]), "=r"(r[11]),
                  "=r"(r[12]), "=r"(r[13]), "=r"(r[14]), "=r"(r[15]),
                  "=r"(r[16]), "=r"(r[17]), "=r"(r[18]), "=r"(r[19]),
                  "=r"(r[20]), "=r"(r[21]), "=r"(r[22]), "=r"(r[23]),
                  "=r"(r[24]), "=r"(r[25]), "=r"(r[26]), "=r"(r[27]),
                  "=r"(r[28]), "=r"(r[29]), "=r"(r[30]), "=r"(r[31])
                : "r"(tmem + h * 64));
            asm volatile(
                "tcgen05.ld.sync.aligned.32x32b.x32.b32 "
                "{%0, %1, %2, %3, %4, %5, %6, %7, "
                " %8, %9, %10, %11, %12, %13, %14, %15, "
                " %16, %17, %18, %19, %20, %21, %22, %23, "
                " %24, %25, %26, %27, %28, %29, %30, %31}, [%32];"
                : "=r"(r[32]), "=r"(r[33]), "=r"(r[34]), "=r"(r[35]),
                  "=r"(r[36]), "=r"(r[37]), "=r"(r[38]), "=r"(r[39]),
                  "=r"(r[40]), "=r"(r[41]), "=r"(r[42]), "=r"(r[43]),
                  "=r"(r[44]), "=r"(r[45]), "=r"(r[46]), "=r"(r[47]),
                  "=r"(r[48]), "=r"(r[49]), "=r"(r[50]), "=r"(r[51]),
                  "=r"(r[52]), "=r"(r[53]), "=r"(r[54]), "=r"(r[55]),
                  "=r"(r[56]), "=r"(r[57]), "=r"(r[58]), "=r"(r[59]),
                  "=r"(r[60]), "=r"(r[61]), "=r"(r[62]), "=r"(r[63])
                : "r"(tmem + h * 64 + 32));
            asm volatile("tcgen05.wait::ld.sync.aligned;" ::: "memory");
            float4* orow = reinterpret_cast<float4*>(out + (size_t)m * ODIM + n0 + h * 64);
            const float4* brow = reinterpret_cast<const float4*>(bias + n0 + h * 64);
#pragma unroll
            for (int c = 0; c < 16; ++c) {
                float4 bv = brow[c];
                float4 v;
                v.x = __uint_as_float(r[4 * c + 0]) * s + bv.x;
                v.y = __uint_as_float(r[4 * c + 1]) * s + bv.y;
                v.z = __uint_as_float(r[4 * c + 2]) * s + bv.z;
                v.w = __uint_as_float(r[4 * c + 3]) * s + bv.w;
                orow[c] = v;
            }
        }
    }
    __syncthreads();
    if (wid == 0) {
        asm volatile("tcgen05.relinquish_alloc_permit.cta_group::2.sync.aligned;");
        asm volatile("tcgen05.dealloc.cta_group::2.sync.aligned.b32 %0, %1;"
                     :: "r"(tmem), "r"(TMEM_NCOLS));
    }
    asm volatile("barrier.cluster.arrive.aligned;" ::: "memory");
    asm volatile("barrier.cluster.wait.aligned;" ::: "memory");

#else
    // =======================================================================
    // Fallback (plain sm_103): mma.sync.m16n8k16 f16/f32, 128x256 CTA tile,
    // 8 warps x (64x64), 4-stage bulk-DMA pipeline.
    // =======================================================================
    int cta = blockIdx.x;
    int mt = cta >> 4;                 // 0..63 (128-row A tile)
    int nt = cta & 15;                 // 0..15 (256-col N tile)
    int n0 = nt * 256;
    int m0 = mt * 128;

    int wm = wid & 1;                  // warp M block (64 rows)
    int wn = wid >> 1;                 // warp N block (64 cols)

    if (tid == 0) {
#pragma unroll
        for (int s = 0; s < F_STAGES; ++s) {
            mbar_init(sbase + SMEM_FULL + 8 * s, 1u);
            mbar_init(sbase + SMEM_EMPTY + 8 * s, 256u);
        }
    }
    __syncthreads();

    const char* Asrc = reinterpret_cast<const char*>(g_Xt + (size_t)mt * 64 * 1024);
    const char* B0src = reinterpret_cast<const char*>(g_Wt + (size_t)(nt * 2) * 64 * 1024);
    const char* B1src = reinterpret_cast<const char*>(g_Wt + (size_t)(nt * 2 + 1) * 64 * 1024);

    if (tid == 0) {
#pragma unroll
        for (int k = 0; k < F_STAGES; ++k) {
            uint32_t fb = sbase + SMEM_FULL + 8 * k;
            uint32_t stg = sbase + SMEM_DATA + k * F_STAGE_BYTES;
            expect_tx(fb, 3 * OP_BYTES);
            bulk_ld(stg,                 Asrc  + (size_t)k * OP_BYTES, OP_BYTES, fb);
            bulk_ld(stg + OP_BYTES,      B0src + (size_t)k * OP_BYTES, OP_BYTES, fb);
            bulk_ld(stg + 2 * OP_BYTES,  B1src + (size_t)k * OP_BYTES, OP_BYTES, fb);
        }
    }

    // Per-thread ldmatrix address components (row*128 base + xor nibble).
    // A x4 tile t: rows = wm*64 + t*16 + (lane&15); 16B col sel = (lane>>4)*16.
    int lrow = lid & 15;
    int lcol16 = (lid >> 4) * 16;
    uint32_t aRow[4], aXor[4];
#pragma unroll
    for (int t = 0; t < 4; ++t) {
        int r = wm * 64 + t * 16 + lrow;
        aRow[t] = (uint32_t)(r * 128);
        aXor[t] = (uint32_t)((r & 7) << 4);
    }
    uint32_t bOff[4], bXor[4];
#pragma unroll
    for (int p = 0; p < 4; ++p) {
        int n = wn * 64 + p * 16 + lrow;       // 0..255
        int half = n >> 7, rl = n & 127;
        bOff[p] = (uint32_t)(half * 16384 + rl * 128);
        bXor[p] = (uint32_t)((rl & 7) << 4);
    }

    float acc[4][8][4];
#pragma unroll
    for (int t = 0; t < 4; ++t)
#pragma unroll
        for (int u = 0; u < 8; ++u)
#pragma unroll
            for (int e = 0; e < 4; ++e) acc[t][u][e] = 0.0f;

    for (int k = 0; k < NCHUNK; ++k) {
        int st = k & (F_STAGES - 1);
        uint32_t par = (uint32_t)((k >> 2) & 1);
        mbar_wait_cta(sbase + SMEM_FULL + 8 * st, par);

        uint32_t sA = sbase + SMEM_DATA + st * F_STAGE_BYTES;
        uint32_t sB = sA + OP_BYTES;

#pragma unroll
        for (int ks = 0; ks < 4; ++ks) {
            uint32_t cb = (uint32_t)(ks * 32 + lcol16);     // byte col within 128B row
            uint32_t a[4][4];
#pragma unroll
            for (int t = 0; t < 4; ++t) {
                uint32_t addr = sA + aRow[t] + (cb ^ aXor[t]);
                asm volatile(
                    "ldmatrix.sync.aligned.m8n8.x4.shared.b16 {%0,%1,%2,%3}, [%4];"
                    : "=r"(a[t][0]), "=r"(a[t][1]), "=r"(a[t][2]), "=r"(a[t][3])
                    : "r"(addr));
            }
            uint32_t b[8][2];
#pragma unroll
            for (int p = 0; p < 4; ++p) {
                uint32_t addr = sB + bOff[p] + (cb ^ bXor[p]);
                uint32_t r0, r1, r2, r3;
                asm volatile(
                    "ldmatrix.sync.aligned.m8n8.x4.shared.b16 {%0,%1,%2,%3}, [%4];"
                    : "=r"(r0), "=r"(r1), "=r"(r2), "=r"(r3)
                    : "r"(addr));
                b[2 * p][0] = r0; b[2 * p][1] = r2;
                b[2 * p + 1][0] = r1; b[2 * p + 1][1] = r3;
            }
#pragma unroll
            for (int t = 0; t < 4; ++t)
#pragma unroll
                for (int u = 0; u < 8; ++u) {
                    asm volatile(
                        "mma.sync.aligned.m16n8k16.row.col.f32.f16.f16.f32 "
                        "{%0,%1,%2,%3}, {%4,%5,%6,%7}, {%8,%9}, {%0,%1,%2,%3};"
                        : "+f"(acc[t][u][0]), "+f"(acc[t][u][1]),
                          "+f"(acc[t][u][2]), "+f"(acc[t][u][3])
                        : "r"(a[t][0]), "r"(a[t][1]), "r"(a[t][2]), "r"(a[t][3]),
                          "r"(b[u][0]), "r"(b[u][1]));
                }
        }

        mbar_arrive(sbase + SMEM_EMPTY + 8 * st);
        if (tid == 0 && k + F_STAGES < NCHUNK) {
            mbar_wait_cta(sbase + SMEM_EMPTY + 8 * st, par);
            uint32_t fb = sbase + SMEM_FULL + 8 * st;
            uint32_t stg = sbase + SMEM_DATA + st * F_STAGE_BYTES;
            expect_tx(fb, 3 * OP_BYTES);
            bulk_ld(stg,                Asrc  + (size_t)(k + F_STAGES) * OP_BYTES, OP_BYTES, fb);
            bulk_ld(stg + OP_BYTES,     B0src + (size_t)(k + F_STAGES) * OP_BYTES, OP_BYTES, fb);
            bulk_ld(stg + 2 * OP_BYTES, B1src + (size_t)(k + F_STAGES) * OP_BYTES, OP_BYTES, fb);
        }
    }

    // Epilogue: d frag (t,u): rows m0+wm*64+16t + lid/4 (+8), cols n0+wn*64+8u+2*(lid%4)
    int qr = lid >> 2;
    int qc = (lid & 3) * 2;
#pragma unroll
    for (int t = 0; t < 4; ++t) {
        int mA = m0 + wm * 64 + t * 16 + qr;
        int mB = mA + 8;
        float sA_ = act_scale[mA & (SEQ - 1)];
        float sB_ = act_scale[mB & (SEQ - 1)];
#pragma unroll
        for (int u = 0; u < 8; ++u) {
            int n = n0 + wn * 64 + u * 8 + qc;
            float b0 = bias[n], b1 = bias[n + 1];
            float2 v0, v1;
            v0.x = acc[t][u][0] * sA_ + b0;
            v0.y = acc[t][u][1] * sA_ + b1;
            v1.x = acc[t][u][2] * sB_ + b0;
            v1.y = acc[t][u][3] * sB_ + b1;
            *reinterpret_cast<float2*>(out + (size_t)mA * ODIM + n) = v0;
            *reinterpret_cast<float2*>(out + (size_t)mB * ODIM + n) = v1;
        }
    }
#endif
}

// ---------------------------------------------------------------------------
extern "C" void kernel_launch(void* const* d_in, const int* in_sizes, int n_in,
                              void* d_out, int out_size) {
    const float* x            = (const float*)d_in[0];
    const int*   qweight      = (const int*)d_in[1];
    const float* act_scale    = (const float*)d_in[2];
    const float* weight_scale = (const float*)d_in[3];
    const int*   weight_zero  = (const int*)d_in[4];
    const float* bias         = (const float*)d_in[5];
    float* out = (float*)d_out;

    cudaFuncSetAttribute(gemm_kernel,
                         cudaFuncAttributeMaxDynamicSharedMemorySize, SMEM_TOTAL);

    quant_x_kernel<<<(MTOT * IDIM / 8) / 256, 256>>>(x, act_scale);
    dequant_w_kernel<<<(ODIM * IDIM / 8) / 256, 256>>>(qweight, weight_scale, weight_zero);
    gemm_kernel<<<1024, 256, SMEM_TOTAL>>>(act_scale, bias, out);
}